// round 1
// baseline (speedup 1.0000x reference)
#include <cuda_runtime.h>

// Shapes (fixed dataset): B=16384, N=200000, K=16, E=256, H=2, A=64, HD=128
#define BB    16384
#define EE    256
#define KK    16
#define AA    64

// Scratch (allocation-free rule: __device__ globals)
__device__ float g_center[BB * EE];
__device__ float g_agg[BB * EE];
__device__ float g_comb[BB * EE];

__device__ __forceinline__ float gelu_exact(float x) {
    return 0.5f * x * (1.0f + erff(x * 0.70710678118654752440f));
}

// ---------------------------------------------------------------------------
// K1: per-b attention. 128 threads per block, one block per batch element.
//  - gather center + 16 neighbor rows to smem
//  - warp 0: center-half MLP dot (shared across k)
//  - all warps: neighbor-half GEMM, k-tile 4 x a-tile 4 register blocking
//  - GELU + W2 -> logits, warp softmax, weighted aggregation
// ---------------------------------------------------------------------------
__global__ __launch_bounds__(128) void k1_attn(
    const int*   __restrict__ center_idx,
    const float* __restrict__ emb,
    const int*   __restrict__ nbidx,
    const float* __restrict__ nbwt,
    const float* __restrict__ W1,   // [2][512][64]
    const float* __restrict__ b1,   // [2][64]
    const float* __restrict__ W2,   // [2][64]
    const float* __restrict__ b2)   // [2]
{
    __shared__ __align__(16) float sNB[16][258];   // pad 258: even (8B lds) + no conflicts
    __shared__ __align__(16) float sC[256];
    __shared__ __align__(16) float scd[128];       // centerdot + b1, indexed by h*64+a
    __shared__ float slog[32];                     // [h][k]
    __shared__ float sWgt[32];                     // softmax weights [h][k]
    __shared__ int   sIdx[16];
    __shared__ float sWt[16];

    const int b   = blockIdx.x;
    const int tid = threadIdx.x;
    const int ci  = center_idx[b];
    const bool valid = (ci >= 0);
    const int safe = valid ? ci : 0;

    if (tid < 16) {
        sIdx[tid] = nbidx[(size_t)safe * 16 + tid];
        sWt[tid]  = nbwt[(size_t)safe * 16 + tid];
    }
    __syncthreads();

    // Gather 17 rows (16 neighbors + center), 64 float4 each
    for (int i = tid; i < 17 * 64; i += 128) {
        const int row = i >> 6;
        const int j4  = (i & 63) * 4;
        if (row < 16) {
            int r = sIdx[row]; if (r < 0) r = 0;
            const float4 v = *(const float4*)(emb + (size_t)r * 256 + j4);
            sNB[row][j4 + 0] = v.x; sNB[row][j4 + 1] = v.y;
            sNB[row][j4 + 2] = v.z; sNB[row][j4 + 3] = v.w;
        } else {
            float4 v = make_float4(0.f, 0.f, 0.f, 0.f);
            if (valid) v = *(const float4*)(emb + (size_t)safe * 256 + j4);
            *(float4*)(sC + j4) = v;
        }
    }
    __syncthreads();

    // --- center-half dot: warp 0 only, vectorized over a (float4) ---
    if (tid < 32) {
        const int hh  = tid >> 4;          // 0..1
        const int aa4 = (tid & 15) * 4;    // 0..60
        const float* wc = W1 + hh * 32768 + aa4;
        float c0 = 0.f, c1 = 0.f, c2 = 0.f, c3 = 0.f;
        #pragma unroll 4
        for (int e = 0; e < 256; e++) {
            const float4 wv = *(const float4*)(wc + (e << 6));
            const float  x  = sC[e];
            c0 = fmaf(x, wv.x, c0); c1 = fmaf(x, wv.y, c1);
            c2 = fmaf(x, wv.z, c2); c3 = fmaf(x, wv.w, c3);
        }
        const float4 b1v = *(const float4*)(b1 + hh * 64 + aa4);
        float4 o; o.x = c0 + b1v.x; o.y = c1 + b1v.y; o.z = c2 + b1v.z; o.w = c3 + b1v.w;
        *(float4*)(scd + hh * 64 + aa4) = o;
    }

    // --- neighbor-half GEMM: [16 x 256] x [256 x 128], k4 x a4 tiles ---
    const int ag  = tid & 31;
    const int h   = ag >> 4;               // head
    const int a4  = (ag & 15) * 4;         // a offset within head
    const int k0  = (tid >> 5) * 4;        // 4 neighbors per warp

    float acc[4][4] = {};
    const float* wp = W1 + h * 32768 + 16384 + a4;   // neighbor half (+256 rows)
    #pragma unroll 2
    for (int e = 0; e < 256; e += 2) {
        const float4 w0 = *(const float4*)(wp + (e << 6));
        const float4 w1 = *(const float4*)(wp + (e << 6) + 64);
        float2 xk[4];
        #pragma unroll
        for (int kk = 0; kk < 4; kk++)
            xk[kk] = *(const float2*)&sNB[k0 + kk][e];
        #pragma unroll
        for (int kk = 0; kk < 4; kk++) {
            acc[kk][0] = fmaf(xk[kk].x, w0.x, acc[kk][0]);
            acc[kk][1] = fmaf(xk[kk].x, w0.y, acc[kk][1]);
            acc[kk][2] = fmaf(xk[kk].x, w0.z, acc[kk][2]);
            acc[kk][3] = fmaf(xk[kk].x, w0.w, acc[kk][3]);
            acc[kk][0] = fmaf(xk[kk].y, w1.x, acc[kk][0]);
            acc[kk][1] = fmaf(xk[kk].y, w1.y, acc[kk][1]);
            acc[kk][2] = fmaf(xk[kk].y, w1.z, acc[kk][2]);
            acc[kk][3] = fmaf(xk[kk].y, w1.w, acc[kk][3]);
        }
    }
    __syncthreads();   // scd ready

    // --- GELU + W2, reduce 16 lanes -> logits ---
    const float4 w2v = *(const float4*)(W2 + h * 64 + a4);
    const float4 cb  = *(const float4*)(scd + h * 64 + a4);
    float p[4];
    #pragma unroll
    for (int kk = 0; kk < 4; kk++) {
        p[kk] = gelu_exact(cb.x + acc[kk][0]) * w2v.x
              + gelu_exact(cb.y + acc[kk][1]) * w2v.y
              + gelu_exact(cb.z + acc[kk][2]) * w2v.z
              + gelu_exact(cb.w + acc[kk][3]) * w2v.w;
        #pragma unroll
        for (int m = 1; m < 16; m <<= 1)
            p[kk] += __shfl_xor_sync(0xffffffffu, p[kk], m);
    }
    if ((tid & 15) == 0) {
        #pragma unroll
        for (int kk = 0; kk < 4; kk++)
            slog[h * 16 + k0 + kk] = p[kk];
    }
    __syncthreads();

    // --- softmax over k (warp 0; 2 independent 16-lane groups, no divergence) ---
    if (tid < 32) {
        const int hh = tid >> 4;
        const int k  = tid & 15;
        const bool msk = (sIdx[k] >= 0);
        const float NEG_INF = __int_as_float(0xff800000);
        float lv = slog[hh * 16 + k] + b2[hh] + logf(sWt[k] + 1e-8f);
        if (!msk) lv = NEG_INF;
        float mx = lv;
        #pragma unroll
        for (int s = 1; s < 16; s <<= 1)
            mx = fmaxf(mx, __shfl_xor_sync(0xffffffffu, mx, s));
        const bool none = (mx == NEG_INF);     // no valid neighbor: uniform weights
        const float mxf = none ? 0.f : mx;
        float ex = msk ? expf(lv - mxf) : 0.f;
        float sm = ex;
        #pragma unroll
        for (int s = 1; s < 16; s <<= 1)
            sm += __shfl_xor_sync(0xffffffffu, sm, s);
        sWgt[hh * 16 + k] = none ? (1.0f / 16.0f) : (ex / sm);
    }
    __syncthreads();

    // --- aggregation + write scratch ---
    for (int e = tid; e < 256; e += 128) {
        const int hh = e >> 7;
        float av = 0.f;
        #pragma unroll
        for (int k = 0; k < 16; k++)
            av = fmaf(sWgt[hh * 16 + k], sNB[k][e], av);
        g_agg[(size_t)b * 256 + e]    = av;
        g_center[(size_t)b * 256 + e] = sC[e];
    }
}

// ---------------------------------------------------------------------------
// K2: gate = sigmoid(c_head @ gate_W[h]^T + gate_b), combined = c + gate*agg
// grid (B/32, 2). 32-b x 128-d tile, smem-staged weight chunks.
// ---------------------------------------------------------------------------
__global__ __launch_bounds__(256) void k2_gate(
    const float* __restrict__ gW,   // [2][128][128]
    const float* __restrict__ gb)   // [2][128]
{
    __shared__ float gws[128][33];   // [d_out][e-chunk] pad 33 -> conflict-free
    __shared__ float cs[32][128];    // c_head tile (broadcast reads, no pad needed)

    const int hh  = blockIdx.y;
    const int b0  = blockIdx.x * 32;
    const int tid = threadIdx.x;

    for (int i = tid; i < 32 * 128; i += 256) {
        const int bb = i >> 7, e = i & 127;
        cs[bb][e] = g_center[(size_t)(b0 + bb) * 256 + hh * 128 + e];
    }

    const int dg = tid & 31;    // d = dg + 32*i  (strided -> conflict-free)
    const int bg = tid >> 5;    // b = bg*4 + j
    float acc[4][4] = {};

    const float* gsrc = gW + hh * 16384;
    for (int ec = 0; ec < 4; ec++) {
        __syncthreads();
        for (int i = tid; i < 128 * 32; i += 256) {
            const int d = i >> 5, e = i & 31;
            gws[d][e] = gsrc[d * 128 + ec * 32 + e];
        }
        __syncthreads();
        #pragma unroll 4
        for (int e = 0; e < 32; e++) {
            float xv[4], wv[4];
            #pragma unroll
            for (int j = 0; j < 4; j++) xv[j] = cs[bg * 4 + j][ec * 32 + e];
            #pragma unroll
            for (int i = 0; i < 4; i++) wv[i] = gws[dg + 32 * i][e];
            #pragma unroll
            for (int j = 0; j < 4; j++)
                #pragma unroll
                for (int i = 0; i < 4; i++)
                    acc[j][i] = fmaf(xv[j], wv[i], acc[j][i]);
        }
    }

    #pragma unroll
    for (int j = 0; j < 4; j++) {
        const int bb = b0 + bg * 4 + j;
        #pragma unroll
        for (int i = 0; i < 4; i++) {
            const int d = dg + 32 * i;
            const float gate = 1.0f / (1.0f + expf(-(acc[j][i] + gb[hh * 128 + d])));
            const size_t idx = (size_t)bb * 256 + hh * 128 + d;
            g_comb[idx] = fmaf(gate, g_agg[idx], cs[bg * 4 + j][d]);
        }
    }
}

// ---------------------------------------------------------------------------
// K3: out = combined @ out_W^T + out_b, then where(valid, out, center)
// grid (B/64, 4). 64x64 tile, 4 e-chunks of 64, 4x4 register tiles.
// ---------------------------------------------------------------------------
__global__ __launch_bounds__(256) void k3_out(
    const float* __restrict__ oW,   // [256][256]
    const float* __restrict__ ob,   // [256]
    const int*   __restrict__ center_idx,
    float*       __restrict__ out)
{
    __shared__ float xs[64][65];
    __shared__ float ws[64][65];

    const int b0  = blockIdx.x * 64;
    const int o0  = blockIdx.y * 64;
    const int tid = threadIdx.x;
    const int tx  = tid & 15;    // o = o0 + tx + 16*i
    const int ty  = tid >> 4;    // b = b0 + ty*4 + j

    float acc[4][4] = {};
    for (int ec = 0; ec < 4; ec++) {
        __syncthreads();
        for (int i = tid; i < 1024; i += 256) {
            const int r = i >> 4, c4 = (i & 15) * 4;
            float4 v = *(const float4*)(g_comb + (size_t)(b0 + r) * 256 + ec * 64 + c4);
            xs[r][c4] = v.x; xs[r][c4 + 1] = v.y; xs[r][c4 + 2] = v.z; xs[r][c4 + 3] = v.w;
            v = *(const float4*)(oW + (size_t)(o0 + r) * 256 + ec * 64 + c4);
            ws[r][c4] = v.x; ws[r][c4 + 1] = v.y; ws[r][c4 + 2] = v.z; ws[r][c4 + 3] = v.w;
        }
        __syncthreads();
        #pragma unroll 4
        for (int e = 0; e < 64; e++) {
            float xv[4], wv[4];
            #pragma unroll
            for (int j = 0; j < 4; j++) xv[j] = xs[ty * 4 + j][e];
            #pragma unroll
            for (int i = 0; i < 4; i++) wv[i] = ws[tx + 16 * i][e];
            #pragma unroll
            for (int j = 0; j < 4; j++)
                #pragma unroll
                for (int i = 0; i < 4; i++)
                    acc[j][i] = fmaf(xv[j], wv[i], acc[j][i]);
        }
    }

    #pragma unroll
    for (int j = 0; j < 4; j++) {
        const int bb = b0 + ty * 4 + j;
        const int ci = center_idx[bb];
        #pragma unroll
        for (int i = 0; i < 4; i++) {
            const int o = o0 + tx + 16 * i;
            float y = acc[j][i] + ob[o];
            if (ci < 0) y = g_center[(size_t)bb * 256 + o];
            out[(size_t)bb * 256 + o] = y;
        }
    }
}

// ---------------------------------------------------------------------------
extern "C" void kernel_launch(void* const* d_in, const int* in_sizes, int n_in,
                              void* d_out, int out_size)
{
    const int*   center_idx = (const int*)  d_in[0];
    const float* emb        = (const float*)d_in[1];
    const int*   nbidx      = (const int*)  d_in[2];
    const float* nbwt       = (const float*)d_in[3];
    const float* W1         = (const float*)d_in[4];
    const float* b1         = (const float*)d_in[5];
    const float* W2         = (const float*)d_in[6];
    const float* b2         = (const float*)d_in[7];
    const float* gW         = (const float*)d_in[8];
    const float* gb         = (const float*)d_in[9];
    const float* oW         = (const float*)d_in[10];
    const float* ob         = (const float*)d_in[11];
    float* out = (float*)d_out;

    const int B = in_sizes[0];   // 16384

    k1_attn<<<B, 128>>>(center_idx, emb, nbidx, nbwt, W1, b1, W2, b2);
    k2_gate<<<dim3(B / 32, 2), 256>>>(gW, gb);
    k3_out<<<dim3(B / 64, 4), 256>>>(oW, ob, center_idx, out);
}

// round 2
// speedup vs baseline: 1.1194x; 1.1194x over previous
#include <cuda_runtime.h>

// Shapes (fixed dataset): B=16384, N=200000, K=16, E=256, H=2, A=64, HD=128
#define BB    16384
#define NBPB  4          // batch elems per k1 block
#define SX_PAD 18

// Scratch (allocation-free rule: __device__ globals)
__device__ float g_center[BB * 256];
__device__ float g_agg[BB * 256];
__device__ float g_comb[BB * 256];

__device__ __forceinline__ float gelu_exact(float x) {
    return 0.5f * x * (1.0f + erff(x * 0.70710678118654752440f));
}

// Blackwell packed fp32: one instruction, two FMAs (ptxas never emits this from C++)
__device__ __forceinline__ unsigned long long dup2(float x) {
    unsigned long long r;
    asm("mov.b64 %0, {%1, %1};" : "=l"(r) : "f"(x));
    return r;
}
__device__ __forceinline__ void fma2(unsigned long long& d, unsigned long long a, unsigned long long b) {
    asm("fma.rn.f32x2 %0, %1, %2, %0;" : "+l"(d) : "l"(a), "l"(b));
}
__device__ __forceinline__ float2 unpack2(unsigned long long v) {
    float2 r;
    asm("mov.b64 {%0, %1}, %2;" : "=f"(r.x), "=f"(r.y) : "l"(v));
    return r;
}

struct K1Smem {
    float sX[NBPB][256][SX_PAD];   // transposed neighbor tile [b][e][k], pad 18
    float sC[NBPB][256];           // center rows
    float scdp[4][NBPB][128];      // center-dot partials per e-quarter
    float scd[NBPB][128];          // reduced center-dot + b1
    float slogp[2][NBPB][2][16];   // logit partials (two a-halves per head)
    float sWgt[NBPB][2][16];       // softmax weights
    int   sIdx[NBPB][16];
    float sWt[NBPB][16];
    int   sCi[NBPB];
};

// ---------------------------------------------------------------------------
// K1: 4 batch elems per 256-thread block.
//   gather -> center-half dot (128 thr) -> neighbor GEMM (FFMA2, b2xk4xa4)
//   -> GELU+W2 -> softmax -> aggregation
// ---------------------------------------------------------------------------
__global__ __launch_bounds__(256) void k1_attn(
    const int*   __restrict__ center_idx,
    const float* __restrict__ emb,
    const int*   __restrict__ nbidx,
    const float* __restrict__ nbwt,
    const float* __restrict__ W1,   // [2][512][64]
    const float* __restrict__ b1,   // [2][64] (contiguous 128)
    const float* __restrict__ W2,   // [2][64] (contiguous 128)
    const float* __restrict__ b2)   // [2]
{
    extern __shared__ __align__(16) char smem_raw[];
    K1Smem& S = *(K1Smem*)smem_raw;

    const int tid = threadIdx.x;
    const int b0  = blockIdx.x * NBPB;

    if (tid < NBPB) S.sCi[tid] = center_idx[b0 + tid];
    __syncthreads();
    if (tid < NBPB * 16) {
        const int bb = tid >> 4, k = tid & 15;
        const int ci = S.sCi[bb];
        const int safe = ci >= 0 ? ci : 0;
        S.sIdx[bb][k] = nbidx[(size_t)safe * 16 + k];
        S.sWt[bb][k]  = nbwt[(size_t)safe * 16 + k];
    }
    __syncthreads();

    // --- gather: 4 x (16 neighbors + center) rows, float4 granularity ---
    for (int i = tid; i < NBPB * 17 * 64; i += 256) {
        const int row = i >> 6;             // 0..67
        const int j4  = (i & 63) * 4;
        const int bb  = row / 17;
        const int r   = row - bb * 17;
        if (r < 16) {
            int idx = S.sIdx[bb][r]; if (idx < 0) idx = 0;
            const float4 v = *(const float4*)(emb + (size_t)idx * 256 + j4);
            S.sX[bb][j4 + 0][r] = v.x; S.sX[bb][j4 + 1][r] = v.y;
            S.sX[bb][j4 + 2][r] = v.z; S.sX[bb][j4 + 3][r] = v.w;
        } else {
            const int ci = S.sCi[bb];
            float4 v = make_float4(0.f, 0.f, 0.f, 0.f);
            if (ci >= 0) v = *(const float4*)(emb + (size_t)ci * 256 + j4);
            *(float4*)&S.sC[bb][j4] = v;
        }
    }
    __syncthreads();

    // --- center-half dot on 128 threads: (eq, h, a4), 4 b's each ---
    if (tid < 128) {
        const int eq = tid >> 5;
        const int hh = (tid >> 4) & 1;
        const int a4 = (tid & 15) * 4;
        const float* wc = W1 + hh * 32768 + a4;     // center half: rows 0..255
        float ac[NBPB][4] = {};
        const int e0 = eq * 64;
        #pragma unroll 4
        for (int e = e0; e < e0 + 64; e++) {
            const float4 wv = *(const float4*)(wc + (size_t)e * 64);
            #pragma unroll
            for (int bb = 0; bb < NBPB; bb++) {
                const float x = S.sC[bb][e];
                ac[bb][0] = fmaf(x, wv.x, ac[bb][0]);
                ac[bb][1] = fmaf(x, wv.y, ac[bb][1]);
                ac[bb][2] = fmaf(x, wv.z, ac[bb][2]);
                ac[bb][3] = fmaf(x, wv.w, ac[bb][3]);
            }
        }
        #pragma unroll
        for (int bb = 0; bb < NBPB; bb++)
            *(float4*)&S.scdp[eq][bb][hh * 64 + a4] =
                make_float4(ac[bb][0], ac[bb][1], ac[bb][2], ac[bb][3]);
    }

    // --- neighbor GEMM: per thread tile b2 x k4 x a4, packed along k ---
    const int warp = tid >> 5;
    const int lane = tid & 31;
    const int bg = warp >> 2;            // b base = bg*2
    const int cg = warp & 3;             // 32-col slice of the 128 (h,a) cols
    const int kg = lane >> 3;            // k0 = kg*4
    const int al = lane & 7;
    const int c0 = cg * 32 + al * 4;     // combined col: h = c0>>6, a = c0&63
    const int hh2 = c0 >> 6;
    const int a0  = c0 & 63;
    const int k0  = kg * 4;
    const int bA  = bg * 2;

    const float* wp = W1 + hh2 * 32768 + 16384 + a0;   // neighbor half (+256 rows)
    const float* xA = &S.sX[bA][0][k0];
    const float* xB = &S.sX[bA + 1][0][k0];

    unsigned long long acc[2][2][4] = {};   // [b][kpair][a]
    #pragma unroll 4
    for (int e = 0; e < 256; e++) {
        const float4 wv = *(const float4*)(wp + (size_t)e * 64);
        const unsigned long long w0 = dup2(wv.x), w1 = dup2(wv.y),
                                 w2 = dup2(wv.z), w3 = dup2(wv.w);
        const unsigned long long xa0 = *(const unsigned long long*)(xA + e * SX_PAD);
        const unsigned long long xa1 = *(const unsigned long long*)(xA + e * SX_PAD + 2);
        const unsigned long long xb0 = *(const unsigned long long*)(xB + e * SX_PAD);
        const unsigned long long xb1 = *(const unsigned long long*)(xB + e * SX_PAD + 2);
        fma2(acc[0][0][0], xa0, w0); fma2(acc[0][0][1], xa0, w1);
        fma2(acc[0][0][2], xa0, w2); fma2(acc[0][0][3], xa0, w3);
        fma2(acc[0][1][0], xa1, w0); fma2(acc[0][1][1], xa1, w1);
        fma2(acc[0][1][2], xa1, w2); fma2(acc[0][1][3], xa1, w3);
        fma2(acc[1][0][0], xb0, w0); fma2(acc[1][0][1], xb0, w1);
        fma2(acc[1][0][2], xb0, w2); fma2(acc[1][0][3], xb0, w3);
        fma2(acc[1][1][0], xb1, w0); fma2(acc[1][1][1], xb1, w1);
        fma2(acc[1][1][2], xb1, w2); fma2(acc[1][1][3], xb1, w3);
    }
    __syncthreads();   // scdp complete (center-dot), GEMM done

    // --- reduce center-dot partials, add b1 ---
    for (int i = tid; i < NBPB * 128; i += 256) {
        const int bb = i >> 7, c = i & 127;
        S.scd[bb][c] = S.scdp[0][bb][c] + S.scdp[1][bb][c]
                     + S.scdp[2][bb][c] + S.scdp[3][bb][c] + b1[c];
    }
    __syncthreads();

    // --- GELU + W2 dot, reduce over the 8 'al' lanes ---
    const float4 w2v = *(const float4*)(W2 + c0);
    #pragma unroll
    for (int bb2 = 0; bb2 < 2; bb2++) {
        const int bb = bA + bb2;
        const float4 cd = *(const float4*)&S.scd[bb][c0];
        #pragma unroll
        for (int kp = 0; kp < 2; kp++) {
            const float2 u0 = unpack2(acc[bb2][kp][0]);
            const float2 u1 = unpack2(acc[bb2][kp][1]);
            const float2 u2 = unpack2(acc[bb2][kp][2]);
            const float2 u3 = unpack2(acc[bb2][kp][3]);
            float plo = gelu_exact(cd.x + u0.x) * w2v.x + gelu_exact(cd.y + u1.x) * w2v.y
                      + gelu_exact(cd.z + u2.x) * w2v.z + gelu_exact(cd.w + u3.x) * w2v.w;
            float phi = gelu_exact(cd.x + u0.y) * w2v.x + gelu_exact(cd.y + u1.y) * w2v.y
                      + gelu_exact(cd.z + u2.y) * w2v.z + gelu_exact(cd.w + u3.y) * w2v.w;
            #pragma unroll
            for (int m = 1; m < 8; m <<= 1) {
                plo += __shfl_xor_sync(0xffffffffu, plo, m);
                phi += __shfl_xor_sync(0xffffffffu, phi, m);
            }
            if (al == 0) {
                S.slogp[cg & 1][bb][hh2][k0 + 2 * kp]     = plo;
                S.slogp[cg & 1][bb][hh2][k0 + 2 * kp + 1] = phi;
            }
        }
    }
    __syncthreads();

    // --- softmax over k: 128 threads, 16-lane shfl groups ---
    if (tid < 128) {
        const int bb = tid >> 5;
        const int hh = (tid >> 4) & 1;
        const int k  = tid & 15;
        const bool msk = (S.sIdx[bb][k] >= 0);
        const float NEG_INF = __int_as_float(0xff800000);
        float lv = S.slogp[0][bb][hh][k] + S.slogp[1][bb][hh][k]
                 + b2[hh] + logf(S.sWt[bb][k] + 1e-8f);
        if (!msk) lv = NEG_INF;
        float mx = lv;
        #pragma unroll
        for (int s = 1; s < 16; s <<= 1)
            mx = fmaxf(mx, __shfl_xor_sync(0xffffffffu, mx, s));
        const bool none = (mx == NEG_INF);
        const float mxf = none ? 0.f : mx;
        float ex = msk ? expf(lv - mxf) : 0.f;
        float sm = ex;
        #pragma unroll
        for (int s = 1; s < 16; s <<= 1)
            sm += __shfl_xor_sync(0xffffffffu, sm, s);
        S.sWgt[bb][hh][k] = none ? (1.0f / 16.0f) : (ex / sm);
    }
    __syncthreads();

    // --- aggregation + write scratch ---
    for (int i = tid; i < NBPB * 256; i += 256) {
        const int bb = i >> 8, e = i & 255;
        const int hh = e >> 7;
        float av = 0.f;
        #pragma unroll
        for (int k = 0; k < 16; k++)
            av = fmaf(S.sWgt[bb][hh][k], S.sX[bb][e][k], av);
        g_agg[(size_t)(b0 + bb) * 256 + e]    = av;
        g_center[(size_t)(b0 + bb) * 256 + e] = S.sC[bb][e];
    }
}

// ---------------------------------------------------------------------------
// K2: gate = sigmoid(c_head @ gate_W[h]^T + gate_b), combined = c + gate*agg
// ---------------------------------------------------------------------------
__global__ __launch_bounds__(256) void k2_gate(
    const float* __restrict__ gW,   // [2][128][128]
    const float* __restrict__ gb)   // [2][128]
{
    __shared__ float gws[128][33];
    __shared__ float cs[32][128];

    const int hh  = blockIdx.y;
    const int b0  = blockIdx.x * 32;
    const int tid = threadIdx.x;

    for (int i = tid; i < 32 * 128; i += 256) {
        const int bb = i >> 7, e = i & 127;
        cs[bb][e] = g_center[(size_t)(b0 + bb) * 256 + hh * 128 + e];
    }

    const int dg = tid & 31;
    const int bg = tid >> 5;
    float acc[4][4] = {};

    const float* gsrc = gW + hh * 16384;
    for (int ec = 0; ec < 4; ec++) {
        __syncthreads();
        for (int i = tid; i < 128 * 32; i += 256) {
            const int d = i >> 5, e = i & 31;
            gws[d][e] = gsrc[d * 128 + ec * 32 + e];
        }
        __syncthreads();
        #pragma unroll 4
        for (int e = 0; e < 32; e++) {
            float xv[4], wv[4];
            #pragma unroll
            for (int j = 0; j < 4; j++) xv[j] = cs[bg * 4 + j][ec * 32 + e];
            #pragma unroll
            for (int i = 0; i < 4; i++) wv[i] = gws[dg + 32 * i][e];
            #pragma unroll
            for (int j = 0; j < 4; j++)
                #pragma unroll
                for (int i = 0; i < 4; i++)
                    acc[j][i] = fmaf(xv[j], wv[i], acc[j][i]);
        }
    }

    #pragma unroll
    for (int j = 0; j < 4; j++) {
        const int bb = b0 + bg * 4 + j;
        #pragma unroll
        for (int i = 0; i < 4; i++) {
            const int d = dg + 32 * i;
            const float gate = 1.0f / (1.0f + expf(-(acc[j][i] + gb[hh * 128 + d])));
            const size_t idx = (size_t)bb * 256 + hh * 128 + d;
            g_comb[idx] = fmaf(gate, g_agg[idx], cs[bg * 4 + j][d]);
        }
    }
}

// ---------------------------------------------------------------------------
// K3: out = combined @ out_W^T + out_b, then where(valid, out, center)
// ---------------------------------------------------------------------------
__global__ __launch_bounds__(256) void k3_out(
    const float* __restrict__ oW,
    const float* __restrict__ ob,
    const int*   __restrict__ center_idx,
    float*       __restrict__ out)
{
    __shared__ float xs[64][65];
    __shared__ float ws[64][65];

    const int b0  = blockIdx.x * 64;
    const int o0  = blockIdx.y * 64;
    const int tid = threadIdx.x;
    const int tx  = tid & 15;
    const int ty  = tid >> 4;

    float acc[4][4] = {};
    for (int ec = 0; ec < 4; ec++) {
        __syncthreads();
        for (int i = tid; i < 1024; i += 256) {
            const int r = i >> 4, c4 = (i & 15) * 4;
            float4 v = *(const float4*)(g_comb + (size_t)(b0 + r) * 256 + ec * 64 + c4);
            xs[r][c4] = v.x; xs[r][c4 + 1] = v.y; xs[r][c4 + 2] = v.z; xs[r][c4 + 3] = v.w;
            v = *(const float4*)(oW + (size_t)(o0 + r) * 256 + ec * 64 + c4);
            ws[r][c4] = v.x; ws[r][c4 + 1] = v.y; ws[r][c4 + 2] = v.z; ws[r][c4 + 3] = v.w;
        }
        __syncthreads();
        #pragma unroll 4
        for (int e = 0; e < 64; e++) {
            float xv[4], wv[4];
            #pragma unroll
            for (int j = 0; j < 4; j++) xv[j] = xs[ty * 4 + j][e];
            #pragma unroll
            for (int i = 0; i < 4; i++) wv[i] = ws[tx + 16 * i][e];
            #pragma unroll
            for (int j = 0; j < 4; j++)
                #pragma unroll
                for (int i = 0; i < 4; i++)
                    acc[j][i] = fmaf(xv[j], wv[i], acc[j][i]);
        }
    }

    #pragma unroll
    for (int j = 0; j < 4; j++) {
        const int bb = b0 + ty * 4 + j;
        const int ci = center_idx[bb];
        #pragma unroll
        for (int i = 0; i < 4; i++) {
            const int o = o0 + tx + 16 * i;
            float y = acc[j][i] + ob[o];
            if (ci < 0) y = g_center[(size_t)bb * 256 + o];
            out[(size_t)bb * 256 + o] = y;
        }
    }
}

// ---------------------------------------------------------------------------
extern "C" void kernel_launch(void* const* d_in, const int* in_sizes, int n_in,
                              void* d_out, int out_size)
{
    const int*   center_idx = (const int*)  d_in[0];
    const float* emb        = (const float*)d_in[1];
    const int*   nbidx      = (const int*)  d_in[2];
    const float* nbwt       = (const float*)d_in[3];
    const float* W1         = (const float*)d_in[4];
    const float* b1         = (const float*)d_in[5];
    const float* W2         = (const float*)d_in[6];
    const float* b2         = (const float*)d_in[7];
    const float* gW         = (const float*)d_in[8];
    const float* gb         = (const float*)d_in[9];
    const float* oW         = (const float*)d_in[10];
    const float* ob         = (const float*)d_in[11];
    float* out = (float*)d_out;

    const int B = in_sizes[0];   // 16384
    const int smem = (int)sizeof(K1Smem);

    cudaFuncSetAttribute(k1_attn, cudaFuncAttributeMaxDynamicSharedMemorySize, smem);
    k1_attn<<<B / NBPB, 256, smem>>>(center_idx, emb, nbidx, nbwt, W1, b1, W2, b2);
    k2_gate<<<dim3(B / 32, 2), 256>>>(gW, gb);
    k3_out<<<dim3(B / 64, 4), 256>>>(oW, ob, center_idx, out);
}